// round 9
// baseline (speedup 1.0000x reference)
#include <cuda_runtime.h>
#include <cuda_fp16.h>
#include <math.h>
#include <stdint.h>

#define PS 32
#define E_DIM 768
#define IMG 1024
#define MAXP 1024
#define MAXTOK 8192
#define KDIM 3072
#define MAXM 7936   // 8 * 992 upper bound on B*n32

// ---------------- device scratch ----------------
__device__ int g_rows[MAXTOK];
__device__ int g_cols[MAXTOK];
__device__ int g_szs[MAXTOK];
__device__ int g_tok32[MAXP];
__device__ int g_tokSm[MAXTOK];
__device__ int g_n32;
__device__ int g_nSm;
__device__ int g_hasS;
__device__ float g_WfT16[768 * E_DIM];
__device__ float g_WfT8[192 * E_DIM];
__device__ float g_WfT4[48 * E_DIM];

// fp16 operands for the HMMA GEMM
__device__ __align__(16) __half g_Ah[(size_t)MAXM * KDIM];   // [m][k]
__device__ __align__(16) __half g_WT[(size_t)KDIM * E_DIM];  // [k][n]

// ---------------- PTX helpers (arch-portable, sm_80-level) ----------------
__device__ __forceinline__ uint32_t smem_u32(const void* p) {
    uint32_t a;
    asm("{ .reg .u64 t; cvta.to.shared.u64 t, %1; cvt.u32.u64 %0, t; }" : "=r"(a) : "l"(p));
    return a;
}
__device__ __forceinline__ void cp16(uint32_t dst, const void* src) {
    asm volatile("cp.async.cg.shared.global [%0], [%1], 16;" :: "r"(dst), "l"(src));
}
__device__ __forceinline__ void ldsm4(uint32_t& r0, uint32_t& r1, uint32_t& r2, uint32_t& r3,
                                      uint32_t addr) {
    asm volatile("ldmatrix.sync.aligned.m8n8.x4.shared.b16 {%0,%1,%2,%3}, [%4];"
                 : "=r"(r0), "=r"(r1), "=r"(r2), "=r"(r3) : "r"(addr));
}
__device__ __forceinline__ void ldsm4t(uint32_t& r0, uint32_t& r1, uint32_t& r2, uint32_t& r3,
                                       uint32_t addr) {
    asm volatile("ldmatrix.sync.aligned.m8n8.x4.trans.shared.b16 {%0,%1,%2,%3}, [%4];"
                 : "=r"(r0), "=r"(r1), "=r"(r2), "=r"(r3) : "r"(addr));
}
__device__ __forceinline__ void mma16816(float* d, const uint32_t* a, uint32_t b0, uint32_t b1) {
    asm volatile("mma.sync.aligned.m16n8k16.row.col.f32.f16.f16.f32 "
                 "{%0,%1,%2,%3}, {%4,%5,%6,%7}, {%8,%9}, {%0,%1,%2,%3};"
                 : "+f"(d[0]), "+f"(d[1]), "+f"(d[2]), "+f"(d[3])
                 : "r"(a[0]), "r"(a[1]), "r"(a[2]), "r"(a[3]), "r"(b0), "r"(b1));
}

// ---------------- layout kernel (replicates _token_layout) ----------------
__global__ void layout_kernel(const float* __restrict__ iw, int P) {
    __shared__ double red[256];
    __shared__ int sz[MAXP];
    int tid = threadIdx.x;
    double s = 0.0;
    for (int i = tid; i < P; i += 256) s += (double)iw[i];
    red[tid] = s;
    __syncthreads();
    for (int o = 128; o > 0; o >>= 1) { if (tid < o) red[tid] += red[tid + o]; __syncthreads(); }
    double avg = red[0] / (double)P;
    double fac = 32.0 * pow(avg, 0.05);
    for (int i = tid; i < P; i += 256) {
        double v = fac / pow((double)iw[i], 0.05);
        if (v > 32.0) v = 32.0;
        double best = fabs(v - 32.0); int bs = 32;
        double d = fabs(v - 16.0); if (d < best) { best = d; bs = 16; }
        d = fabs(v - 8.0);  if (d < best) { best = d; bs = 8; }
        d = fabs(v - 4.0);  if (d < best) { best = d; bs = 4; }
        sz[i] = bs;
    }
    __syncthreads();
    if (tid == 0) {
        int off = 0, n32 = 0, nSm = 0, has = 0;
        for (int i = 0; i < P; i++) {
            int si = sz[i];
            int ini_col = (i * PS) % IMG;
            int ini_row = (i * PS * PS) / IMG;
            if (si > 3 && si < PS) {
                int ns = PS / si;
                if (si == 16) has |= 1; else if (si == 8) has |= 2; else has |= 4;
                for (int j = 0; j < ns; j++) {
                    g_rows[off] = ini_row + (j * si) / ns;
                    g_cols[off] = ini_col + (j * si) % (ns * si);
                    g_szs[off]  = si;
                    g_tokSm[nSm++] = off; off++;
                }
            } else {
                g_rows[off] = ini_row; g_cols[off] = ini_col; g_szs[off] = PS;
                g_tok32[n32++] = off; off++;
            }
        }
        g_n32 = n32; g_nSm = nSm; g_hasS = has;
    }
}

// ---------------- folded weights for small tokens ----------------
__global__ void prep_wf(const float* __restrict__ W) {
    int has = g_hasS;
    const int n16 = 768 * E_DIM, n8 = 192 * E_DIM, n4 = 48 * E_DIM;
    int total = n16 + n8 + n4;
    for (int idx = blockIdx.x * blockDim.x + threadIdx.x; idx < total;
         idx += gridDim.x * blockDim.x) {
        int s, K, id; float* dst;
        if (idx < n16)           { if (!(has & 1)) continue; s = 16; K = 768; id = idx;            dst = g_WfT16; }
        else if (idx < n16 + n8) { if (!(has & 2)) continue; s = 8;  K = 192; id = idx - n16;      dst = g_WfT8; }
        else                     { if (!(has & 4)) continue; s = 4;  K = 48;  id = idx - n16 - n8; dst = g_WfT4; }
        int e = id / K, k = id - e * K;
        int ss = s * s, c = k / ss, rem = k - c * ss, h = rem / s, w = rem - h * s;
        int kd = PS / s;
        const float* base = W + e * (3 * PS * PS) + c * (PS * PS) + h * s + w;
        float acc = 0.f;
        for (int a = 0; a < kd; a++)
            for (int b2 = 0; b2 < kd; b2++) acc += base[a * (kd * ss) + b2 * ss];
        dst[k * E_DIM + e] = acc;
    }
}

// ---------------- W transpose + fp16 convert: g_WT[k][n] ----------------
__global__ void transposeW_kernel(const float* __restrict__ W) {
    __shared__ __half s[32][33];
    int k0 = blockIdx.x * 32, n0 = blockIdx.y * 32;
    int tx = threadIdx.x, ty = threadIdx.y;  // (32, 8)
#pragma unroll
    for (int i = 0; i < 4; i++) {
        int nl = ty + i * 8;
        s[nl][tx] = __float2half(W[(size_t)(n0 + nl) * KDIM + k0 + tx]);
    }
    __syncthreads();
#pragma unroll
    for (int i = 0; i < 4; i++) {
        int kl = ty + i * 8;
        g_WT[(size_t)(k0 + kl) * E_DIM + n0 + tx] = s[tx][kl];
    }
}

// ---------------- gather s=32 patch rows into fp16 A [m][k] ----------------
__global__ void gatherA_kernel(const float* __restrict__ x, int B) {
    int idx = blockIdx.x * 256 + threadIdx.x;   // one 8-fp16 (16B) chunk
    if (idx >= MAXM * (KDIM / 8)) return;
    int m = idx / (KDIM / 8), q = idx - m * (KDIM / 8);
    int k = q * 8;
    int Mtot = B * g_n32;
    uint4 u = make_uint4(0u, 0u, 0u, 0u);
    if (m < Mtot) {
        int tokpos = m / B, b = m - tokpos * B;
        int t = g_tok32[tokpos];
        int c = k >> 10, rem = k & 1023, h = rem >> 5, w = rem & 31;
        const float* src = x + (size_t)((b * 3 + c) * IMG + g_rows[t] + h) * IMG + g_cols[t] + w;
        float4 v0 = __ldcs((const float4*)src);
        float4 v1 = __ldcs((const float4*)(src + 4));
        __half2 h0 = __floats2half2_rn(v0.x, v0.y);
        __half2 h1 = __floats2half2_rn(v0.z, v0.w);
        __half2 h2 = __floats2half2_rn(v1.x, v1.y);
        __half2 h3 = __floats2half2_rn(v1.z, v1.w);
        u.x = *(uint32_t*)&h0; u.y = *(uint32_t*)&h1;
        u.z = *(uint32_t*)&h2; u.w = *(uint32_t*)&h3;
    }
    __stcs((uint4*)(g_Ah + (size_t)m * KDIM + k), u);
}

// ---------------- HMMA GEMM: CTA 128x128, 4 warps (warp tile 64x64), BK=64, 3-stage ----------------
#define BKG 64
#define KT (KDIM / BKG)          // 48
#define STAGE_B_OFF 16384        // A: 128*64*2=16KB, B: 64*128*2=16KB
#define STAGE_SZ 32768
#define SM_GEMM (1024 + 3 * STAGE_SZ)   // 99328

__device__ __forceinline__ void issue_stage(int ch, uint32_t bA, uint32_t bB,
                                            int tid, int m0, int n0) {
    const int kel = ch * BKG;
#pragma unroll
    for (int i = 0; i < 8; i++) {
        int j = tid + 128 * i;
        int m = j >> 3, c = j & 7;
        const __half* src = g_Ah + (size_t)(m0 + m) * KDIM + kel + c * 8;
        cp16(bA + m * 128 + ((c ^ (m & 7)) << 4), src);
    }
#pragma unroll
    for (int i = 0; i < 8; i++) {
        int j = tid + 128 * i;
        int k = j >> 4, c = j & 15;
        const __half* src = g_WT + (size_t)(kel + k) * E_DIM + n0 + c * 8;
        cp16(bB + k * 256 + ((c ^ (k & 7)) << 4), src);
    }
    asm volatile("cp.async.commit_group;" ::: "memory");
}

__global__ __launch_bounds__(128) void gemm_hmma(const float* __restrict__ bias,
                                                 float* __restrict__ out, int B, int T) {
    extern __shared__ char smem[];
    int* s_ro = (int*)smem;
    const uint32_t sbase = smem_u32(smem);
    const int tid = threadIdx.x;
    const int lane = tid & 31, wid = tid >> 5;
    const int Mtot = B * g_n32;
    const int m0 = blockIdx.y * 128;
    if (m0 >= Mtot) return;
    const int n0 = blockIdx.x * 128;

    {
        int m = m0 + tid;
        if (m < Mtot) {
            int tp = m / B, b = m - tp * B;
            int t = g_tok32[tp];
            s_ro[tid] = (b * T + t) * E_DIM;
        } else s_ro[tid] = -1;
    }

    const int warp_m = wid & 1;   // 0..1 (64 rows each)
    const int warp_n = wid >> 1;  // 0..1 (64 cols each)

    uint32_t bufA[3], bufB[3];
#pragma unroll
    for (int s = 0; s < 3; s++) {
        bufA[s] = sbase + 1024 + s * STAGE_SZ;
        bufB[s] = bufA[s] + STAGE_B_OFF;
    }

    // ldmatrix lane-invariant address parts
    const int rowA = warp_m * 64 + (lane & 15);
    const int chA  = lane >> 4;
    const int rswA = rowA & 7;
    const int kB   = lane & 15;
    const int cB0  = warp_n * 8 + (lane >> 4);
    const int kswB = lane & 7;

    float acc[4][8][4];
#pragma unroll
    for (int i = 0; i < 4; i++)
#pragma unroll
        for (int j = 0; j < 8; j++)
#pragma unroll
            for (int q = 0; q < 4; q++) acc[i][j][q] = 0.f;

    issue_stage(0, bufA[0], bufB[0], tid, m0, n0);
    issue_stage(1, bufA[1], bufB[1], tid, m0, n0);

    for (int kt = 0; kt < KT; kt++) {
        asm volatile("cp.async.wait_group 1;" ::: "memory");
        __syncthreads();
        if (kt + 2 < KT) {
            int s2 = (kt + 2) % 3;
            issue_stage(kt + 2, bufA[s2], bufB[s2], tid, m0, n0);
        } else {
            asm volatile("cp.async.commit_group;" ::: "memory");
        }
        const int s = kt % 3;
        const uint32_t bA = bufA[s], bB = bufB[s];
#pragma unroll
        for (int ks = 0; ks < 4; ks++) {
            uint32_t a[4][4], b[4][4];
#pragma unroll
            for (int mi = 0; mi < 4; mi++) {
                uint32_t addr = bA + (rowA + mi * 16) * 128 + (((ks * 2 + chA) ^ rswA) << 4);
                ldsm4(a[mi][0], a[mi][1], a[mi][2], a[mi][3], addr);
            }
#pragma unroll
            for (int nj = 0; nj < 4; nj++) {
                uint32_t addr = bB + (ks * 16 + kB) * 256 + (((cB0 + nj * 2) ^ kswB) << 4);
                ldsm4t(b[nj][0], b[nj][1], b[nj][2], b[nj][3], addr);
            }
#pragma unroll
            for (int mi = 0; mi < 4; mi++)
#pragma unroll
                for (int ni = 0; ni < 8; ni++) {
                    uint32_t b0 = b[ni >> 1][(ni & 1) * 2];
                    uint32_t b1 = b[ni >> 1][(ni & 1) * 2 + 1];
                    mma16816(acc[mi][ni], a[mi], b0, b1);
                }
        }
    }

    // epilogue
    const int mrow_base = warp_m * 64 + (lane >> 2);
    const int nb = n0 + warp_n * 64 + (lane & 3) * 2;
    float2 bv[8];
#pragma unroll
    for (int ni = 0; ni < 8; ni++) bv[ni] = make_float2(bias[nb + ni * 8], bias[nb + ni * 8 + 1]);
#pragma unroll
    for (int mi = 0; mi < 4; mi++) {
#pragma unroll
        for (int h = 0; h < 2; h++) {
            int row = mrow_base + mi * 16 + h * 8;
            int ro = s_ro[row];
            if (ro < 0) continue;
#pragma unroll
            for (int ni = 0; ni < 8; ni++) {
                float2 v = make_float2(acc[mi][ni][h * 2 + 0] + bv[ni].x,
                                       acc[mi][ni][h * 2 + 1] + bv[ni].y);
                *(float2*)(out + ro + nb + ni * 8) = v;
            }
        }
    }
}

// ---------------- small tokens: 768 threads, 1 output/thread ----------------
__global__ __launch_bounds__(768) void small_kernel(const float* __restrict__ x,
                                                    const float* __restrict__ bias,
                                                    float* __restrict__ out, int B, int T) {
    __shared__ float patch[3072];
    const int nSm = g_nSm;
    const int total = nSm * B;
    const int tid = threadIdx.x;
    for (int wrk = blockIdx.x; wrk < total; wrk += gridDim.x) {
        int pos = wrk / B, b = wrk - pos * B;
        int t = g_tokSm[pos];
        int s = g_szs[t];
        int prow = g_rows[t], pcol = g_cols[t];
        int ss = s * s, K = 3 * ss;
        const float* WfT = (s == 16) ? g_WfT16 : (s == 8) ? g_WfT8 : g_WfT4;
        for (int k = tid; k < K; k += 768) {
            int c = k / ss, rem = k - c * ss, h = rem / s, w = rem - h * s;
            patch[k] = x[(size_t)((b * 3 + c) * IMG + prow + h) * IMG + pcol + w];
        }
        __syncthreads();
        float a = bias[tid];
#pragma unroll 8
        for (int k = 0; k < K; k++) a = fmaf(patch[k], WfT[(size_t)k * E_DIM + tid], a);
        out[(size_t)(b * T + t) * E_DIM + tid] = a;
        __syncthreads();
    }
}

// ---------------- launch ----------------
extern "C" void kernel_launch(void* const* d_in, const int* in_sizes, int n_in,
                              void* d_out, int out_size) {
    const float* x    = (const float*)d_in[0];
    const float* iw   = (const float*)d_in[1];
    const float* W    = (const float*)d_in[2];
    const float* bias = (const float*)d_in[3];

    int P = in_sizes[1];
    int B = in_sizes[0] / (3 * IMG * IMG);
    int T = out_size / (B * E_DIM);

    layout_kernel<<<1, 256>>>(iw, P);
    prep_wf<<<256, 256>>>(W);
    transposeW_kernel<<<dim3(KDIM / 32, E_DIM / 32), dim3(32, 8)>>>(W);
    gatherA_kernel<<<(MAXM * (KDIM / 8) + 255) / 256, 256>>>(x, B);

    cudaFuncSetAttribute(gemm_hmma, cudaFuncAttributeMaxDynamicSharedMemorySize, SM_GEMM);
    gemm_hmma<<<dim3(E_DIM / 128, MAXM / 128), 128, SM_GEMM>>>(bias, (float*)d_out, B, T);
    small_kernel<<<64, 768>>>(x, bias, (float*)d_out, B, T);
}

// round 10
// speedup vs baseline: 1.0049x; 1.0049x over previous
#include <cuda_runtime.h>
#include <cuda_fp16.h>
#include <math.h>
#include <stdint.h>

#define PS 32
#define E_DIM 768
#define IMG 1024
#define MAXP 1024
#define MAXTOK 8192
#define KDIM 3072
#define MAXM 7936   // 8 * 992 upper bound on B*n32

// ---------------- device scratch ----------------
__device__ int g_rows[MAXTOK];
__device__ int g_cols[MAXTOK];
__device__ int g_szs[MAXTOK];
__device__ int g_tok32[MAXP];
__device__ int g_tokSm[MAXTOK];
__device__ int g_n32;
__device__ int g_nSm;
__device__ int g_hasS;
__device__ float g_WfT16[768 * E_DIM];
__device__ float g_WfT8[192 * E_DIM];
__device__ float g_WfT4[48 * E_DIM];

// fp16 operands for the HMMA GEMM
__device__ __align__(16) __half g_Ah[(size_t)MAXM * KDIM];   // [m][k]
__device__ __align__(16) __half g_WT[(size_t)KDIM * E_DIM];  // [k][n]

// ---------------- PTX helpers (arch-portable, sm_80-level) ----------------
__device__ __forceinline__ uint32_t smem_u32(const void* p) {
    uint32_t a;
    asm("{ .reg .u64 t; cvta.to.shared.u64 t, %1; cvt.u32.u64 %0, t; }" : "=r"(a) : "l"(p));
    return a;
}
__device__ __forceinline__ void cp16(uint32_t dst, const void* src) {
    asm volatile("cp.async.cg.shared.global [%0], [%1], 16;" :: "r"(dst), "l"(src));
}
__device__ __forceinline__ void ldsm4(uint32_t& r0, uint32_t& r1, uint32_t& r2, uint32_t& r3,
                                      uint32_t addr) {
    asm volatile("ldmatrix.sync.aligned.m8n8.x4.shared.b16 {%0,%1,%2,%3}, [%4];"
                 : "=r"(r0), "=r"(r1), "=r"(r2), "=r"(r3) : "r"(addr));
}
__device__ __forceinline__ void ldsm4t(uint32_t& r0, uint32_t& r1, uint32_t& r2, uint32_t& r3,
                                       uint32_t addr) {
    asm volatile("ldmatrix.sync.aligned.m8n8.x4.trans.shared.b16 {%0,%1,%2,%3}, [%4];"
                 : "=r"(r0), "=r"(r1), "=r"(r2), "=r"(r3) : "r"(addr));
}
__device__ __forceinline__ void mma16816(float* d, const uint32_t* a, uint32_t b0, uint32_t b1) {
    asm volatile("mma.sync.aligned.m16n8k16.row.col.f32.f16.f16.f32 "
                 "{%0,%1,%2,%3}, {%4,%5,%6,%7}, {%8,%9}, {%0,%1,%2,%3};"
                 : "+f"(d[0]), "+f"(d[1]), "+f"(d[2]), "+f"(d[3])
                 : "r"(a[0]), "r"(a[1]), "r"(a[2]), "r"(a[3]), "r"(b0), "r"(b1));
}

// ---------------- layout kernel (replicates _token_layout) ----------------
__global__ void layout_kernel(const float* __restrict__ iw, int P) {
    __shared__ double red[256];
    __shared__ int sz[MAXP];
    int tid = threadIdx.x;
    double s = 0.0;
    for (int i = tid; i < P; i += 256) s += (double)iw[i];
    red[tid] = s;
    __syncthreads();
    for (int o = 128; o > 0; o >>= 1) { if (tid < o) red[tid] += red[tid + o]; __syncthreads(); }
    double avg = red[0] / (double)P;
    double fac = 32.0 * pow(avg, 0.05);
    for (int i = tid; i < P; i += 256) {
        double v = fac / pow((double)iw[i], 0.05);
        if (v > 32.0) v = 32.0;
        double best = fabs(v - 32.0); int bs = 32;
        double d = fabs(v - 16.0); if (d < best) { best = d; bs = 16; }
        d = fabs(v - 8.0);  if (d < best) { best = d; bs = 8; }
        d = fabs(v - 4.0);  if (d < best) { best = d; bs = 4; }
        sz[i] = bs;
    }
    __syncthreads();
    if (tid == 0) {
        int off = 0, n32 = 0, nSm = 0, has = 0;
        for (int i = 0; i < P; i++) {
            int si = sz[i];
            int ini_col = (i * PS) % IMG;
            int ini_row = (i * PS * PS) / IMG;
            if (si > 3 && si < PS) {
                int ns = PS / si;
                if (si == 16) has |= 1; else if (si == 8) has |= 2; else has |= 4;
                for (int j = 0; j < ns; j++) {
                    g_rows[off] = ini_row + (j * si) / ns;
                    g_cols[off] = ini_col + (j * si) % (ns * si);
                    g_szs[off]  = si;
                    g_tokSm[nSm++] = off; off++;
                }
            } else {
                g_rows[off] = ini_row; g_cols[off] = ini_col; g_szs[off] = PS;
                g_tok32[n32++] = off; off++;
            }
        }
        g_n32 = n32; g_nSm = nSm; g_hasS = has;
    }
}

// ---------------- folded weights for small tokens ----------------
__global__ void prep_wf(const float* __restrict__ W) {
    int has = g_hasS;
    const int n16 = 768 * E_DIM, n8 = 192 * E_DIM, n4 = 48 * E_DIM;
    int total = n16 + n8 + n4;
    for (int idx = blockIdx.x * blockDim.x + threadIdx.x; idx < total;
         idx += gridDim.x * blockDim.x) {
        int s, K, id; float* dst;
        if (idx < n16)           { if (!(has & 1)) continue; s = 16; K = 768; id = idx;            dst = g_WfT16; }
        else if (idx < n16 + n8) { if (!(has & 2)) continue; s = 8;  K = 192; id = idx - n16;      dst = g_WfT8; }
        else                     { if (!(has & 4)) continue; s = 4;  K = 48;  id = idx - n16 - n8; dst = g_WfT4; }
        int e = id / K, k = id - e * K;
        int ss = s * s, c = k / ss, rem = k - c * ss, h = rem / s, w = rem - h * s;
        int kd = PS / s;
        const float* base = W + e * (3 * PS * PS) + c * (PS * PS) + h * s + w;
        float acc = 0.f;
        for (int a = 0; a < kd; a++)
            for (int b2 = 0; b2 < kd; b2++) acc += base[a * (kd * ss) + b2 * ss];
        dst[k * E_DIM + e] = acc;
    }
}

// ---------------- W transpose + fp16 convert: g_WT[k][n] ----------------
__global__ void transposeW_kernel(const float* __restrict__ W) {
    __shared__ __half s[32][33];
    int k0 = blockIdx.x * 32, n0 = blockIdx.y * 32;
    int tx = threadIdx.x, ty = threadIdx.y;  // (32, 8)
#pragma unroll
    for (int i = 0; i < 4; i++) {
        int nl = ty + i * 8;
        s[nl][tx] = __float2half(W[(size_t)(n0 + nl) * KDIM + k0 + tx]);
    }
    __syncthreads();
#pragma unroll
    for (int i = 0; i < 4; i++) {
        int kl = ty + i * 8;
        g_WT[(size_t)(k0 + kl) * E_DIM + n0 + tx] = s[tx][kl];
    }
}

// ---------------- gather s=32 patch rows into fp16 A [m][k] ----------------
__global__ void gatherA_kernel(const float* __restrict__ x, int B) {
    int idx = blockIdx.x * 256 + threadIdx.x;   // one 8-fp16 (16B) chunk
    if (idx >= MAXM * (KDIM / 8)) return;
    int m = idx / (KDIM / 8), q = idx - m * (KDIM / 8);
    int k = q * 8;
    int Mtot = B * g_n32;
    uint4 u = make_uint4(0u, 0u, 0u, 0u);
    if (m < Mtot) {
        int tokpos = m / B, b = m - tokpos * B;
        int t = g_tok32[tokpos];
        int c = k >> 10, rem = k & 1023, h = rem >> 5, w = rem & 31;
        const float* src = x + (size_t)((b * 3 + c) * IMG + g_rows[t] + h) * IMG + g_cols[t] + w;
        float4 v0 = __ldcs((const float4*)src);
        float4 v1 = __ldcs((const float4*)(src + 4));
        __half2 h0 = __floats2half2_rn(v0.x, v0.y);
        __half2 h1 = __floats2half2_rn(v0.z, v0.w);
        __half2 h2 = __floats2half2_rn(v1.x, v1.y);
        __half2 h3 = __floats2half2_rn(v1.z, v1.w);
        u.x = *(uint32_t*)&h0; u.y = *(uint32_t*)&h1;
        u.z = *(uint32_t*)&h2; u.w = *(uint32_t*)&h3;
    }
    __stcs((uint4*)(g_Ah + (size_t)m * KDIM + k), u);
}

// ---------------- HMMA GEMM: CTA 128x128, 4 warps (warp tile 64x64), BK=64, 3-stage ----------------
#define BKG 64
#define KT (KDIM / BKG)          // 48
#define STAGE_B_OFF 16384        // A: 128*64*2=16KB, B: 64*128*2=16KB
#define STAGE_SZ 32768
#define SM_GEMM (1024 + 3 * STAGE_SZ)   // 99328

__device__ __forceinline__ void issue_stage(int ch, uint32_t bA, uint32_t bB,
                                            int tid, int m0, int n0) {
    const int kel = ch * BKG;
#pragma unroll
    for (int i = 0; i < 8; i++) {
        int j = tid + 128 * i;
        int m = j >> 3, c = j & 7;
        const __half* src = g_Ah + (size_t)(m0 + m) * KDIM + kel + c * 8;
        cp16(bA + m * 128 + ((c ^ (m & 7)) << 4), src);
    }
#pragma unroll
    for (int i = 0; i < 8; i++) {
        int j = tid + 128 * i;
        int k = j >> 4, c = j & 15;
        const __half* src = g_WT + (size_t)(kel + k) * E_DIM + n0 + c * 8;
        cp16(bB + k * 256 + ((c ^ (k & 7)) << 4), src);
    }
    asm volatile("cp.async.commit_group;" ::: "memory");
}

__global__ __launch_bounds__(128) void gemm_hmma(const float* __restrict__ bias,
                                                 float* __restrict__ out, int B, int T) {
    extern __shared__ char smem[];
    int* s_ro = (int*)smem;
    const uint32_t sbase = smem_u32(smem);
    const int tid = threadIdx.x;
    const int lane = tid & 31, wid = tid >> 5;
    const int Mtot = B * g_n32;
    const int m0 = blockIdx.y * 128;
    if (m0 >= Mtot) return;
    const int n0 = blockIdx.x * 128;

    {
        int m = m0 + tid;
        if (m < Mtot) {
            int tp = m / B, b = m - tp * B;
            int t = g_tok32[tp];
            s_ro[tid] = (b * T + t) * E_DIM;
        } else s_ro[tid] = -1;
    }

    const int warp_m = wid & 1;   // 0..1 (64 rows each)
    const int warp_n = wid >> 1;  // 0..1 (64 cols each)

    uint32_t bufA[3], bufB[3];
#pragma unroll
    for (int s = 0; s < 3; s++) {
        bufA[s] = sbase + 1024 + s * STAGE_SZ;
        bufB[s] = bufA[s] + STAGE_B_OFF;
    }

    // ldmatrix lane-invariant address parts
    const int rowA = warp_m * 64 + (lane & 15);
    const int chA  = lane >> 4;
    const int rswA = rowA & 7;
    const int kB   = lane & 15;
    const int cB0  = warp_n * 8 + (lane >> 4);
    const int kswB = lane & 7;

    float acc[4][8][4];
#pragma unroll
    for (int i = 0; i < 4; i++)
#pragma unroll
        for (int j = 0; j < 8; j++)
#pragma unroll
            for (int q = 0; q < 4; q++) acc[i][j][q] = 0.f;

    issue_stage(0, bufA[0], bufB[0], tid, m0, n0);
    issue_stage(1, bufA[1], bufB[1], tid, m0, n0);

    for (int kt = 0; kt < KT; kt++) {
        asm volatile("cp.async.wait_group 1;" ::: "memory");
        __syncthreads();
        if (kt + 2 < KT) {
            int s2 = (kt + 2) % 3;
            issue_stage(kt + 2, bufA[s2], bufB[s2], tid, m0, n0);
        } else {
            asm volatile("cp.async.commit_group;" ::: "memory");
        }
        const int s = kt % 3;
        const uint32_t bA = bufA[s], bB = bufB[s];
#pragma unroll
        for (int ks = 0; ks < 4; ks++) {
            uint32_t a[4][4], b[4][4];
#pragma unroll
            for (int mi = 0; mi < 4; mi++) {
                uint32_t addr = bA + (rowA + mi * 16) * 128 + (((ks * 2 + chA) ^ rswA) << 4);
                ldsm4(a[mi][0], a[mi][1], a[mi][2], a[mi][3], addr);
            }
#pragma unroll
            for (int nj = 0; nj < 4; nj++) {
                uint32_t addr = bB + (ks * 16 + kB) * 256 + (((cB0 + nj * 2) ^ kswB) << 4);
                ldsm4t(b[nj][0], b[nj][1], b[nj][2], b[nj][3], addr);
            }
#pragma unroll
            for (int mi = 0; mi < 4; mi++)
#pragma unroll
                for (int ni = 0; ni < 8; ni++) {
                    uint32_t b0 = b[ni >> 1][(ni & 1) * 2];
                    uint32_t b1 = b[ni >> 1][(ni & 1) * 2 + 1];
                    mma16816(acc[mi][ni], a[mi], b0, b1);
                }
        }
    }

    // epilogue
    const int mrow_base = warp_m * 64 + (lane >> 2);
    const int nb = n0 + warp_n * 64 + (lane & 3) * 2;
    float2 bv[8];
#pragma unroll
    for (int ni = 0; ni < 8; ni++) bv[ni] = make_float2(bias[nb + ni * 8], bias[nb + ni * 8 + 1]);
#pragma unroll
    for (int mi = 0; mi < 4; mi++) {
#pragma unroll
        for (int h = 0; h < 2; h++) {
            int row = mrow_base + mi * 16 + h * 8;
            int ro = s_ro[row];
            if (ro < 0) continue;
#pragma unroll
            for (int ni = 0; ni < 8; ni++) {
                float2 v = make_float2(acc[mi][ni][h * 2 + 0] + bv[ni].x,
                                       acc[mi][ni][h * 2 + 1] + bv[ni].y);
                *(float2*)(out + ro + nb + ni * 8) = v;
            }
        }
    }
}

// ---------------- small tokens: 768 threads, 1 output/thread ----------------
__global__ __launch_bounds__(768) void small_kernel(const float* __restrict__ x,
                                                    const float* __restrict__ bias,
                                                    float* __restrict__ out, int B, int T) {
    __shared__ float patch[3072];
    const int nSm = g_nSm;
    const int total = nSm * B;
    const int tid = threadIdx.x;
    for (int wrk = blockIdx.x; wrk < total; wrk += gridDim.x) {
        int pos = wrk / B, b = wrk - pos * B;
        int t = g_tokSm[pos];
        int s = g_szs[t];
        int prow = g_rows[t], pcol = g_cols[t];
        int ss = s * s, K = 3 * ss;
        const float* WfT = (s == 16) ? g_WfT16 : (s == 8) ? g_WfT8 : g_WfT4;
        for (int k = tid; k < K; k += 768) {
            int c = k / ss, rem = k - c * ss, h = rem / s, w = rem - h * s;
            patch[k] = x[(size_t)((b * 3 + c) * IMG + prow + h) * IMG + pcol + w];
        }
        __syncthreads();
        float a = bias[tid];
#pragma unroll 8
        for (int k = 0; k < K; k++) a = fmaf(patch[k], WfT[(size_t)k * E_DIM + tid], a);
        out[(size_t)(b * T + t) * E_DIM + tid] = a;
        __syncthreads();
    }
}

// ---------------- launch ----------------
extern "C" void kernel_launch(void* const* d_in, const int* in_sizes, int n_in,
                              void* d_out, int out_size) {
    const float* x    = (const float*)d_in[0];
    const float* iw   = (const float*)d_in[1];
    const float* W    = (const float*)d_in[2];
    const float* bias = (const float*)d_in[3];

    int P = in_sizes[1];
    int B = in_sizes[0] / (3 * IMG * IMG);
    int T = out_size / (B * E_DIM);

    layout_kernel<<<1, 256>>>(iw, P);
    prep_wf<<<256, 256>>>(W);
    transposeW_kernel<<<dim3(KDIM / 32, E_DIM / 32), dim3(32, 8)>>>(W);
    gatherA_kernel<<<(MAXM * (KDIM / 8) + 255) / 256, 256>>>(x, B);

    cudaFuncSetAttribute(gemm_hmma, cudaFuncAttributeMaxDynamicSharedMemorySize, SM_GEMM);
    gemm_hmma<<<dim3(E_DIM / 128, MAXM / 128), 128, SM_GEMM>>>(bias, (float*)d_out, B, T);
    small_kernel<<<64, 768>>>(x, bias, (float*)d_out, B, T);
}

// round 11
// speedup vs baseline: 1.0090x; 1.0041x over previous
#include <cuda_runtime.h>
#include <cuda_fp16.h>
#include <math.h>
#include <stdint.h>

#define PS 32
#define E_DIM 768
#define IMG 1024
#define MAXP 1024
#define MAXTOK 8192
#define KDIM 3072
#define MAXM 7936   // 8 * 992 upper bound on B*n32

// ---------------- device scratch ----------------
__device__ int g_rows[MAXTOK];
__device__ int g_cols[MAXTOK];
__device__ int g_szs[MAXTOK];
__device__ int g_tok32[MAXP];
__device__ int g_tokSm[MAXTOK];
__device__ int g_n32;
__device__ int g_nSm;
__device__ int g_hasS;
__device__ float g_WfT16[768 * E_DIM];
__device__ float g_WfT8[192 * E_DIM];
__device__ float g_WfT4[48 * E_DIM];

// fp16 operands for the HMMA GEMM
__device__ __align__(16) __half g_Ah[(size_t)MAXM * KDIM];   // [m][k]
__device__ __align__(16) __half g_WT[(size_t)KDIM * E_DIM];  // [k][n]

// ---------------- PTX helpers (arch-portable, sm_80-level) ----------------
__device__ __forceinline__ uint32_t smem_u32(const void* p) {
    uint32_t a;
    asm("{ .reg .u64 t; cvta.to.shared.u64 t, %1; cvt.u32.u64 %0, t; }" : "=r"(a) : "l"(p));
    return a;
}
__device__ __forceinline__ void cp16(uint32_t dst, const void* src) {
    asm volatile("cp.async.cg.shared.global [%0], [%1], 16;" :: "r"(dst), "l"(src));
}
__device__ __forceinline__ void ldsm4(uint32_t& r0, uint32_t& r1, uint32_t& r2, uint32_t& r3,
                                      uint32_t addr) {
    asm volatile("ldmatrix.sync.aligned.m8n8.x4.shared.b16 {%0,%1,%2,%3}, [%4];"
                 : "=r"(r0), "=r"(r1), "=r"(r2), "=r"(r3) : "r"(addr));
}
__device__ __forceinline__ void ldsm4t(uint32_t& r0, uint32_t& r1, uint32_t& r2, uint32_t& r3,
                                       uint32_t addr) {
    asm volatile("ldmatrix.sync.aligned.m8n8.x4.trans.shared.b16 {%0,%1,%2,%3}, [%4];"
                 : "=r"(r0), "=r"(r1), "=r"(r2), "=r"(r3) : "r"(addr));
}
__device__ __forceinline__ void mma16816(float* d, const uint32_t* a, uint32_t b0, uint32_t b1) {
    asm volatile("mma.sync.aligned.m16n8k16.row.col.f32.f16.f16.f32 "
                 "{%0,%1,%2,%3}, {%4,%5,%6,%7}, {%8,%9}, {%0,%1,%2,%3};"
                 : "+f"(d[0]), "+f"(d[1]), "+f"(d[2]), "+f"(d[3])
                 : "r"(a[0]), "r"(a[1]), "r"(a[2]), "r"(a[3]), "r"(b0), "r"(b1));
}

// ---------------- layout kernel (replicates _token_layout) ----------------
__global__ void layout_kernel(const float* __restrict__ iw, int P) {
    __shared__ double red[256];
    __shared__ int sz[MAXP];
    int tid = threadIdx.x;
    double s = 0.0;
    for (int i = tid; i < P; i += 256) s += (double)iw[i];
    red[tid] = s;
    __syncthreads();
    for (int o = 128; o > 0; o >>= 1) { if (tid < o) red[tid] += red[tid + o]; __syncthreads(); }
    double avg = red[0] / (double)P;
    double fac = 32.0 * pow(avg, 0.05);
    for (int i = tid; i < P; i += 256) {
        double v = fac / pow((double)iw[i], 0.05);
        if (v > 32.0) v = 32.0;
        double best = fabs(v - 32.0); int bs = 32;
        double d = fabs(v - 16.0); if (d < best) { best = d; bs = 16; }
        d = fabs(v - 8.0);  if (d < best) { best = d; bs = 8; }
        d = fabs(v - 4.0);  if (d < best) { best = d; bs = 4; }
        sz[i] = bs;
    }
    __syncthreads();
    if (tid == 0) {
        int off = 0, n32 = 0, nSm = 0, has = 0;
        for (int i = 0; i < P; i++) {
            int si = sz[i];
            int ini_col = (i * PS) % IMG;
            int ini_row = (i * PS * PS) / IMG;
            if (si > 3 && si < PS) {
                int ns = PS / si;
                if (si == 16) has |= 1; else if (si == 8) has |= 2; else has |= 4;
                for (int j = 0; j < ns; j++) {
                    g_rows[off] = ini_row + (j * si) / ns;
                    g_cols[off] = ini_col + (j * si) % (ns * si);
                    g_szs[off]  = si;
                    g_tokSm[nSm++] = off; off++;
                }
            } else {
                g_rows[off] = ini_row; g_cols[off] = ini_col; g_szs[off] = PS;
                g_tok32[n32++] = off; off++;
            }
        }
        g_n32 = n32; g_nSm = nSm; g_hasS = has;
    }
}

// ---------------- folded weights for small tokens ----------------
__global__ void prep_wf(const float* __restrict__ W) {
    int has = g_hasS;
    const int n16 = 768 * E_DIM, n8 = 192 * E_DIM, n4 = 48 * E_DIM;
    int total = n16 + n8 + n4;
    for (int idx = blockIdx.x * blockDim.x + threadIdx.x; idx < total;
         idx += gridDim.x * blockDim.x) {
        int s, K, id; float* dst;
        if (idx < n16)           { if (!(has & 1)) continue; s = 16; K = 768; id = idx;            dst = g_WfT16; }
        else if (idx < n16 + n8) { if (!(has & 2)) continue; s = 8;  K = 192; id = idx - n16;      dst = g_WfT8; }
        else                     { if (!(has & 4)) continue; s = 4;  K = 48;  id = idx - n16 - n8; dst = g_WfT4; }
        int e = id / K, k = id - e * K;
        int ss = s * s, c = k / ss, rem = k - c * ss, h = rem / s, w = rem - h * s;
        int kd = PS / s;
        const float* base = W + e * (3 * PS * PS) + c * (PS * PS) + h * s + w;
        float acc = 0.f;
        for (int a = 0; a < kd; a++)
            for (int b2 = 0; b2 < kd; b2++) acc += base[a * (kd * ss) + b2 * ss];
        dst[k * E_DIM + e] = acc;
    }
}

// ---------------- W transpose + fp16 convert: g_WT[k][n] ----------------
__global__ void transposeW_kernel(const float* __restrict__ W) {
    __shared__ __half s[32][33];
    int k0 = blockIdx.x * 32, n0 = blockIdx.y * 32;
    int tx = threadIdx.x, ty = threadIdx.y;  // (32, 8)
#pragma unroll
    for (int i = 0; i < 4; i++) {
        int nl = ty + i * 8;
        s[nl][tx] = __float2half(W[(size_t)(n0 + nl) * KDIM + k0 + tx]);
    }
    __syncthreads();
#pragma unroll
    for (int i = 0; i < 4; i++) {
        int kl = ty + i * 8;
        g_WT[(size_t)(k0 + kl) * E_DIM + n0 + tx] = s[tx][kl];
    }
}

// ---------------- gather s=32 patch rows into fp16 A [m][k] ----------------
__global__ void gatherA_kernel(const float* __restrict__ x, int B) {
    int idx = blockIdx.x * 256 + threadIdx.x;   // one 8-fp16 (16B) chunk
    if (idx >= MAXM * (KDIM / 8)) return;
    int m = idx / (KDIM / 8), q = idx - m * (KDIM / 8);
    int k = q * 8;
    int Mtot = B * g_n32;
    uint4 u = make_uint4(0u, 0u, 0u, 0u);
    if (m < Mtot) {
        int tokpos = m / B, b = m - tokpos * B;
        int t = g_tok32[tokpos];
        int c = k >> 10, rem = k & 1023, h = rem >> 5, w = rem & 31;
        const float* src = x + (size_t)((b * 3 + c) * IMG + g_rows[t] + h) * IMG + g_cols[t] + w;
        float4 v0 = __ldcs((const float4*)src);
        float4 v1 = __ldcs((const float4*)(src + 4));
        __half2 h0 = __floats2half2_rn(v0.x, v0.y);
        __half2 h1 = __floats2half2_rn(v0.z, v0.w);
        __half2 h2 = __floats2half2_rn(v1.x, v1.y);
        __half2 h3 = __floats2half2_rn(v1.z, v1.w);
        u.x = *(uint32_t*)&h0; u.y = *(uint32_t*)&h1;
        u.z = *(uint32_t*)&h2; u.w = *(uint32_t*)&h3;
    }
    __stcs((uint4*)(g_Ah + (size_t)m * KDIM + k), u);
}

// ---------------- HMMA GEMM: CTA 128x128, 4 warps (warp tile 64x64), BK=64, 3-stage ----------------
#define BKG 64
#define KT (KDIM / BKG)          // 48
#define STAGE_B_OFF 16384        // A: 128*64*2=16KB, B: 64*128*2=16KB
#define STAGE_SZ 32768
#define SM_GEMM (1024 + 3 * STAGE_SZ)   // 99328

__device__ __forceinline__ void issue_stage(int ch, uint32_t bA, uint32_t bB,
                                            int tid, int m0, int n0) {
    const int kel = ch * BKG;
#pragma unroll
    for (int i = 0; i < 8; i++) {
        int j = tid + 128 * i;
        int m = j >> 3, c = j & 7;
        const __half* src = g_Ah + (size_t)(m0 + m) * KDIM + kel + c * 8;
        cp16(bA + m * 128 + ((c ^ (m & 7)) << 4), src);
    }
#pragma unroll
    for (int i = 0; i < 8; i++) {
        int j = tid + 128 * i;
        int k = j >> 4, c = j & 15;
        const __half* src = g_WT + (size_t)(kel + k) * E_DIM + n0 + c * 8;
        cp16(bB + k * 256 + ((c ^ (k & 7)) << 4), src);
    }
    asm volatile("cp.async.commit_group;" ::: "memory");
}

__global__ __launch_bounds__(128) void gemm_hmma(const float* __restrict__ bias,
                                                 float* __restrict__ out, int B, int T) {
    extern __shared__ char smem[];
    int* s_ro = (int*)smem;
    const uint32_t sbase = smem_u32(smem);
    const int tid = threadIdx.x;
    const int lane = tid & 31, wid = tid >> 5;
    const int Mtot = B * g_n32;
    const int m0 = blockIdx.y * 128;
    if (m0 >= Mtot) return;
    const int n0 = blockIdx.x * 128;

    {
        int m = m0 + tid;
        if (m < Mtot) {
            int tp = m / B, b = m - tp * B;
            int t = g_tok32[tp];
            s_ro[tid] = (b * T + t) * E_DIM;
        } else s_ro[tid] = -1;
    }

    const int warp_m = wid & 1;   // 0..1 (64 rows each)
    const int warp_n = wid >> 1;  // 0..1 (64 cols each)

    uint32_t bufA[3], bufB[3];
#pragma unroll
    for (int s = 0; s < 3; s++) {
        bufA[s] = sbase + 1024 + s * STAGE_SZ;
        bufB[s] = bufA[s] + STAGE_B_OFF;
    }

    // ldmatrix lane-invariant address parts
    const int rowA = warp_m * 64 + (lane & 15);
    const int chA  = lane >> 4;
    const int rswA = rowA & 7;
    const int kB   = lane & 15;
    const int cB0  = warp_n * 8 + (lane >> 4);
    const int kswB = lane & 7;

    float acc[4][8][4];
#pragma unroll
    for (int i = 0; i < 4; i++)
#pragma unroll
        for (int j = 0; j < 8; j++)
#pragma unroll
            for (int q = 0; q < 4; q++) acc[i][j][q] = 0.f;

    issue_stage(0, bufA[0], bufB[0], tid, m0, n0);
    issue_stage(1, bufA[1], bufB[1], tid, m0, n0);

    for (int kt = 0; kt < KT; kt++) {
        asm volatile("cp.async.wait_group 1;" ::: "memory");
        __syncthreads();
        if (kt + 2 < KT) {
            int s2 = (kt + 2) % 3;
            issue_stage(kt + 2, bufA[s2], bufB[s2], tid, m0, n0);
        } else {
            asm volatile("cp.async.commit_group;" ::: "memory");
        }
        const int s = kt % 3;
        const uint32_t bA = bufA[s], bB = bufB[s];
#pragma unroll
        for (int ks = 0; ks < 4; ks++) {
            uint32_t a[4][4], b[4][4];
#pragma unroll
            for (int mi = 0; mi < 4; mi++) {
                uint32_t addr = bA + (rowA + mi * 16) * 128 + (((ks * 2 + chA) ^ rswA) << 4);
                ldsm4(a[mi][0], a[mi][1], a[mi][2], a[mi][3], addr);
            }
#pragma unroll
            for (int nj = 0; nj < 4; nj++) {
                uint32_t addr = bB + (ks * 16 + kB) * 256 + (((cB0 + nj * 2) ^ kswB) << 4);
                ldsm4t(b[nj][0], b[nj][1], b[nj][2], b[nj][3], addr);
            }
#pragma unroll
            for (int mi = 0; mi < 4; mi++)
#pragma unroll
                for (int ni = 0; ni < 8; ni++) {
                    uint32_t b0 = b[ni >> 1][(ni & 1) * 2];
                    uint32_t b1 = b[ni >> 1][(ni & 1) * 2 + 1];
                    mma16816(acc[mi][ni], a[mi], b0, b1);
                }
        }
    }

    // epilogue
    const int mrow_base = warp_m * 64 + (lane >> 2);
    const int nb = n0 + warp_n * 64 + (lane & 3) * 2;
    float2 bv[8];
#pragma unroll
    for (int ni = 0; ni < 8; ni++) bv[ni] = make_float2(bias[nb + ni * 8], bias[nb + ni * 8 + 1]);
#pragma unroll
    for (int mi = 0; mi < 4; mi++) {
#pragma unroll
        for (int h = 0; h < 2; h++) {
            int row = mrow_base + mi * 16 + h * 8;
            int ro = s_ro[row];
            if (ro < 0) continue;
#pragma unroll
            for (int ni = 0; ni < 8; ni++) {
                float2 v = make_float2(acc[mi][ni][h * 2 + 0] + bv[ni].x,
                                       acc[mi][ni][h * 2 + 1] + bv[ni].y);
                *(float2*)(out + ro + nb + ni * 8) = v;
            }
        }
    }
}

// ---------------- small tokens: 768 threads, 1 output/thread ----------------
__global__ __launch_bounds__(768) void small_kernel(const float* __restrict__ x,
                                                    const float* __restrict__ bias,
                                                    float* __restrict__ out, int B, int T) {
    __shared__ float patch[3072];
    const int nSm = g_nSm;
    const int total = nSm * B;
    const int tid = threadIdx.x;
    for (int wrk = blockIdx.x; wrk < total; wrk += gridDim.x) {
        int pos = wrk / B, b = wrk - pos * B;
        int t = g_tokSm[pos];
        int s = g_szs[t];
        int prow = g_rows[t], pcol = g_cols[t];
        int ss = s * s, K = 3 * ss;
        const float* WfT = (s == 16) ? g_WfT16 : (s == 8) ? g_WfT8 : g_WfT4;
        for (int k = tid; k < K; k += 768) {
            int c = k / ss, rem = k - c * ss, h = rem / s, w = rem - h * s;
            patch[k] = x[(size_t)((b * 3 + c) * IMG + prow + h) * IMG + pcol + w];
        }
        __syncthreads();
        float a = bias[tid];
#pragma unroll 8
        for (int k = 0; k < K; k++) a = fmaf(patch[k], WfT[(size_t)k * E_DIM + tid], a);
        out[(size_t)(b * T + t) * E_DIM + tid] = a;
        __syncthreads();
    }
}

// ---------------- launch ----------------
extern "C" void kernel_launch(void* const* d_in, const int* in_sizes, int n_in,
                              void* d_out, int out_size) {
    const float* x    = (const float*)d_in[0];
    const float* iw   = (const float*)d_in[1];
    const float* W    = (const float*)d_in[2];
    const float* bias = (const float*)d_in[3];

    int P = in_sizes[1];
    int B = in_sizes[0] / (3 * IMG * IMG);
    int T = out_size / (B * E_DIM);

    layout_kernel<<<1, 256>>>(iw, P);
    prep_wf<<<256, 256>>>(W);
    transposeW_kernel<<<dim3(KDIM / 32, E_DIM / 32), dim3(32, 8)>>>(W);
    gatherA_kernel<<<(MAXM * (KDIM / 8) + 255) / 256, 256>>>(x, B);

    cudaFuncSetAttribute(gemm_hmma, cudaFuncAttributeMaxDynamicSharedMemorySize, SM_GEMM);
    gemm_hmma<<<dim3(E_DIM / 128, MAXM / 128), 128, SM_GEMM>>>(bias, (float*)d_out, B, T);
    small_kernel<<<64, 768>>>(x, bias, (float*)d_out, B, T);
}